// round 1
// baseline (speedup 1.0000x reference)
#include <cuda_runtime.h>
#include <cstdint>

// out = x * (1 - mask), mask broadcasts over C.
// x:    [B=64, C=3, H=512, W=512] f32
// mask: [B=64, 1,   H=512, W=512] f32
// HW = 262144 (divisible by 4 -> float4)

static constexpr int Cc = 3;
static constexpr int HW = 512 * 512;
static constexpr int HW4 = HW / 4;       // 65536 float4 per plane
static constexpr int THREADS = 256;

__global__ __launch_bounds__(THREADS, 8)
void random_mask_kernel(const float4* __restrict__ x,
                        const float4* __restrict__ mask,
                        float4* __restrict__ out) {
    // blockIdx.y = b*C + c  (plane index into x/out)
    // blockIdx.x covers the plane in float4 units
    const int bc = blockIdx.y;
    const int b  = bc / Cc;                 // cheap: small int div by const
    const int v  = blockIdx.x * THREADS + threadIdx.x;   // 0..HW4-1

    const long long xi = (long long)bc * HW4 + v;
    const long long mi = (long long)b  * HW4 + v;

    float4 xv = x[xi];
    float4 mv = mask[mi];

    float4 ov;
    ov.x = xv.x * (1.0f - mv.x);
    ov.y = xv.y * (1.0f - mv.y);
    ov.z = xv.z * (1.0f - mv.z);
    ov.w = xv.w * (1.0f - mv.w);

    out[xi] = ov;
}

extern "C" void kernel_launch(void* const* d_in, const int* in_sizes, int n_in,
                              void* d_out, int out_size) {
    const float4* x    = (const float4*)d_in[0];
    const float4* mask = (const float4*)d_in[1];
    float4* out        = (float4*)d_out;

    const int B = in_sizes[1] / HW;         // 64
    dim3 grid(HW4 / THREADS, B * Cc);       // (256, 192)
    random_mask_kernel<<<grid, THREADS>>>(x, mask, out);
}

// round 3
// speedup vs baseline: 1.0027x; 1.0027x over previous
#include <cuda_runtime.h>
#include <cstdint>

// out = x * (1 - mask), mask broadcasts over C=3.
// x:    [B=64, C=3, H=512, W=512] f32
// mask: [B=64, 1,   H=512, W=512] f32
//
// Channel loop moved inside the thread: 1 mask load (registers) feeds all
// 3 channel planes -> mask traffic exactly 1x, MLP=4 independent LDG.128.

static constexpr int Cc = 3;
static constexpr int HW = 512 * 512;
static constexpr int HW4 = HW / 4;       // 65536 float4 per plane
static constexpr int THREADS = 256;

__global__ __launch_bounds__(THREADS, 8)
void random_mask_kernel(const float4* __restrict__ x,
                        const float4* __restrict__ mask,
                        float4* __restrict__ out) {
    const int b = blockIdx.y;                               // batch
    const int v = blockIdx.x * THREADS + threadIdx.x;       // 0..HW4-1

    const long long mi = (long long)b * HW4 + v;
    const long long x0 = (long long)(b * Cc) * HW4 + v;

    // Issue all loads up front for maximum MLP.
    const float4 mv  = mask[mi];
    const float4 xv0 = x[x0];
    const float4 xv1 = x[x0 + HW4];
    const float4 xv2 = x[x0 + 2 * HW4];

    float4 w;
    w.x = 1.0f - mv.x;
    w.y = 1.0f - mv.y;
    w.z = 1.0f - mv.z;
    w.w = 1.0f - mv.w;

    float4 o0, o1, o2;
    o0.x = xv0.x * w.x; o0.y = xv0.y * w.y; o0.z = xv0.z * w.z; o0.w = xv0.w * w.w;
    o1.x = xv1.x * w.x; o1.y = xv1.y * w.y; o1.z = xv1.z * w.z; o1.w = xv1.w * w.w;
    o2.x = xv2.x * w.x; o2.y = xv2.y * w.y; o2.z = xv2.z * w.z; o2.w = xv2.w * w.w;

    out[x0]           = o0;
    out[x0 + HW4]     = o1;
    out[x0 + 2 * HW4] = o2;
}

extern "C" void kernel_launch(void* const* d_in, const int* in_sizes, int n_in,
                              void* d_out, int out_size) {
    const float4* x    = (const float4*)d_in[0];
    const float4* mask = (const float4*)d_in[1];
    float4* out        = (float4*)d_out;

    const int B = in_sizes[1] / HW;          // 64
    dim3 grid(HW4 / THREADS, B);             // (256, 64)
    random_mask_kernel<<<grid, THREADS>>>(x, mask, out);
}